// round 4
// baseline (speedup 1.0000x reference)
#include <cuda_runtime.h>
#include <cuda_bf16.h>
#include <math.h>

#define NV 50000
#define EE 800000
#define ET (EE + NV)        // edges incl. self loops
#define FIN 256
#define HID 64
#define HEADS 4
#define D1 (HEADS * HID)    // 256

typedef unsigned long long ull;

// ---------------- scratch -----------------------------------------------------
__device__ float g_xh1[NV * D1];
__device__ float g_h1[NV * D1];
__device__ float g_xh2[NV * HID];
__device__ float g_als1[NV * HEADS];
__device__ float g_ald1[NV * HEADS];
__device__ float g_als2[NV];
__device__ float g_ald2[NV];
__device__ float g_inv1[NV * HEADS];
__device__ float g_inv2[NV];
__device__ float g_t1[ET * HEADS];   // unnormalized exp per CSR slot (layer1, 4 heads)
__device__ float g_t2[ET];           // layer2
__device__ int   g_rowptr[NV + 1];
__device__ int   g_deg[NV];          // degree -> cursor
__device__ int   g_elist[ET];        // src node per CSR slot

// ---------------- helpers ------------------------------------------------------
__device__ __forceinline__ float lrelu(float v) { return v > 0.f ? v : 0.2f * v; }

__device__ __forceinline__ void edge_sd(const int* __restrict__ ei, int e, int& s, int& d) {
    if (e < EE) { s = ei[e]; d = ei[EE + e]; }
    else        { s = e - EE; d = s; }
}

#define FMA2(acc, a, b) asm("fma.rn.f32x2 %0, %1, %2, %3;" : "=l"(acc) : "l"(a), "l"(b), "l"(acc))
#define PACK2(out, v)   asm("mov.b64 %0, {%1, %1};" : "=l"(out) : "r"(__float_as_uint(v)))
#define UNPACK2(lo, hi, in) asm("mov.b64 {%0, %1}, %2;" : "=r"(lo), "=r"(hi) : "l"(in))

// ---------------- CSR build ----------------------------------------------------
__global__ void deg_init() {
    int i = blockIdx.x * blockDim.x + threadIdx.x;
    if (i < NV) g_deg[i] = 1;   // self loop
}
__global__ void deg_hist(const int* __restrict__ ei) {
    int e = blockIdx.x * blockDim.x + threadIdx.x;
    if (e < EE) atomicAdd(&g_deg[ei[EE + e]], 1);
}
__global__ void scan_k() {
    __shared__ int ssum[1024];
    const int CH = (NV + 1023) / 1024;
    int t = threadIdx.x;
    int base = t * CH;
    int s = 0;
    for (int j = 0; j < CH; j++) { int i = base + j; if (i < NV) s += g_deg[i]; }
    ssum[t] = s;
    __syncthreads();
    for (int off = 1; off < 1024; off <<= 1) {
        int v = (t >= off) ? ssum[t - off] : 0;
        __syncthreads();
        ssum[t] += v;
        __syncthreads();
    }
    int off = (t == 0) ? 0 : ssum[t - 1];
    for (int j = 0; j < CH; j++) {
        int i = base + j;
        if (i < NV) {
            int d = g_deg[i];
            g_rowptr[i] = off;
            g_deg[i] = off;   // cursor
            off += d;
        }
    }
    if (t == 0) g_rowptr[NV] = ET;
}
__global__ void scatter_k(const int* __restrict__ ei) {
    int e = blockIdx.x * blockDim.x + threadIdx.x;
    if (e >= ET) return;
    int s, d; edge_sd(ei, e, s, d);
    int pos = atomicAdd(&g_deg[d], 1);
    g_elist[pos] = s;
}

// ---------------- GEMM A: 128x128 tile, 8x8 micro, f32x2 ------------------------
// C[M,N] = A[M,K] @ B[K,N]. N multiple of 128, K multiple of 8.
__global__ void sgemm128(const float* __restrict__ A, const float* __restrict__ B,
                         float* __restrict__ C, int M, int N, int K) {
    __shared__ float As[8][128];   // As[k][m]
    __shared__ float Bs[8][128];   // Bs[k][n]
    int tid = threadIdx.x;
    int tx = tid & 15, ty = tid >> 4;
    int rowBase = blockIdx.y * 128, colBase = blockIdx.x * 128;
    int m0 = ty * 8, n0 = tx * 8;

    // load indices
    int arow = tid >> 1;            // 0..127
    int akc  = (tid & 1) * 4;       // 0 or 4
    int brow = tid >> 5;            // 0..7
    int bcol = (tid & 31) * 4;      // 0..124

    ull acc[4][8];
#pragma unroll
    for (int i = 0; i < 4; i++)
#pragma unroll
        for (int j = 0; j < 8; j++) acc[i][j] = 0ull;

    for (int k0 = 0; k0 < K; k0 += 8) {
        // A tile: 128 rows x 8 k
        {
            int gr = rowBase + arow;
            float4 a4 = make_float4(0.f, 0.f, 0.f, 0.f);
            if (gr < M) a4 = *(const float4*)&A[(size_t)gr * K + k0 + akc];
            As[akc + 0][arow] = a4.x;
            As[akc + 1][arow] = a4.y;
            As[akc + 2][arow] = a4.z;
            As[akc + 3][arow] = a4.w;
        }
        // B tile: 8 rows x 128 cols
        {
            float4 b4 = *(const float4*)&B[(size_t)(k0 + brow) * N + colBase + bcol];
            *(float4*)&Bs[brow][bcol] = b4;
        }
        __syncthreads();
#pragma unroll
        for (int k = 0; k < 8; k++) {
            ull ap[4];
            const ull* pa = (const ull*)&As[k][m0];
#pragma unroll
            for (int i = 0; i < 4; i++) ap[i] = pa[i];
            float4 b0 = *(const float4*)&Bs[k][n0];
            float4 b1 = *(const float4*)&Bs[k][n0 + 4];
            ull bd[8];
            PACK2(bd[0], b0.x); PACK2(bd[1], b0.y); PACK2(bd[2], b0.z); PACK2(bd[3], b0.w);
            PACK2(bd[4], b1.x); PACK2(bd[5], b1.y); PACK2(bd[6], b1.z); PACK2(bd[7], b1.w);
#pragma unroll
            for (int mp = 0; mp < 4; mp++)
#pragma unroll
                for (int n = 0; n < 8; n++) FMA2(acc[mp][n], ap[mp], bd[n]);
        }
        __syncthreads();
    }
    // epilogue: 8 rows x 8 cols per thread
#pragma unroll
    for (int mp = 0; mp < 4; mp++) {
        int r0 = rowBase + m0 + 2 * mp;
        float lo[8], hi[8];
#pragma unroll
        for (int n = 0; n < 8; n++) {
            unsigned l, h;
            UNPACK2(l, h, acc[mp][n]);
            lo[n] = __uint_as_float(l);
            hi[n] = __uint_as_float(h);
        }
        int col = colBase + n0;
        if (r0 < M) {
            *(float4*)&C[(size_t)r0 * N + col]     = *(float4*)&lo[0];
            *(float4*)&C[(size_t)r0 * N + col + 4] = *(float4*)&lo[4];
        }
        if (r0 + 1 < M) {
            *(float4*)&C[(size_t)(r0 + 1) * N + col]     = *(float4*)&hi[0];
            *(float4*)&C[(size_t)(r0 + 1) * N + col + 4] = *(float4*)&hi[4];
        }
    }
}

// ---------------- GEMM B: 128x64 tile, 8x4 micro, f32x2 (for layer 2) ----------
__global__ void sgemm64(const float* __restrict__ A, const float* __restrict__ B,
                        float* __restrict__ C, int M, int N, int K) {
    __shared__ float As[16][128];
    __shared__ float Bs[16][64];
    int tid = threadIdx.x;
    int tx = tid & 15, ty = tid >> 4;
    int rowBase = blockIdx.y * 128, colBase = blockIdx.x * 64;
    ull acc[4][4];
#pragma unroll
    for (int i = 0; i < 4; i++)
#pragma unroll
        for (int j = 0; j < 4; j++) acc[i][j] = 0ull;

    for (int k0 = 0; k0 < K; k0 += 16) {
#pragma unroll
        for (int i = 0; i < 8; i++) {
            int idx = tid + i * 256;
            int r = idx >> 4, c = idx & 15;
            int gr = rowBase + r;
            As[c][r] = (gr < M) ? A[(size_t)gr * K + k0 + c] : 0.f;
        }
#pragma unroll
        for (int i = 0; i < 4; i++) {
            int idx = tid + i * 256;
            int r = idx >> 6, c = idx & 63;
            Bs[r][c] = B[(size_t)(k0 + r) * N + colBase + c];
        }
        __syncthreads();
#pragma unroll
        for (int k = 0; k < 16; k++) {
            ull ap[4];
            const ull* pa = (const ull*)&As[k][ty * 8];
#pragma unroll
            for (int mp = 0; mp < 4; mp++) ap[mp] = pa[mp];
            float4 bv = *(const float4*)&Bs[k][tx * 4];
            ull bd0, bd1, bd2, bd3;
            PACK2(bd0, bv.x); PACK2(bd1, bv.y); PACK2(bd2, bv.z); PACK2(bd3, bv.w);
#pragma unroll
            for (int mp = 0; mp < 4; mp++) {
                FMA2(acc[mp][0], ap[mp], bd0);
                FMA2(acc[mp][1], ap[mp], bd1);
                FMA2(acc[mp][2], ap[mp], bd2);
                FMA2(acc[mp][3], ap[mp], bd3);
            }
        }
        __syncthreads();
    }
#pragma unroll
    for (int mp = 0; mp < 4; mp++) {
        int r0 = rowBase + ty * 8 + 2 * mp;
#pragma unroll
        for (int n = 0; n < 4; n++) {
            unsigned lo, hi;
            UNPACK2(lo, hi, acc[mp][n]);
            int col = colBase + tx * 4 + n;
            if (r0 < M)     C[(size_t)r0 * N + col]       = __uint_as_float(lo);
            if (r0 + 1 < M) C[(size_t)(r0 + 1) * N + col] = __uint_as_float(hi);
        }
    }
}

// ---------------- attention dots: warp per (node*head) --------------------------
__global__ void attn_dots(const float* __restrict__ xh, const float* __restrict__ asrc,
                          const float* __restrict__ adst, float* __restrict__ als,
                          float* __restrict__ ald, int NH, int H) {
    int w = (blockIdx.x * blockDim.x + threadIdx.x) >> 5;
    if (w >= NH) return;
    int lane = threadIdx.x & 31;
    int h = w % H;
    const float* row = xh + (size_t)w * 64;
    float x0 = row[lane], x1 = row[lane + 32];
    float s = x0 * asrc[h * 64 + lane] + x1 * asrc[h * 64 + lane + 32];
    float d = x0 * adst[h * 64 + lane] + x1 * adst[h * 64 + lane + 32];
#pragma unroll
    for (int o = 16; o; o >>= 1) {
        s += __shfl_down_sync(0xFFFFFFFFu, s, o);
        d += __shfl_down_sync(0xFFFFFFFFu, d, o);
    }
    if (lane == 0) { als[w] = s; ald[w] = d; }
}

// ---------------- softmax layer1: warp per node ----------------------------------
// computes t[j] = exp(lrelu(als[s]+ald[d]) - m) per slot and inv = 1/den per node/head
__global__ void soft1(const float* __restrict__ als, const float* __restrict__ ald) {
    int node = (blockIdx.x * blockDim.x + threadIdx.x) >> 5;
    if (node >= NV) return;
    int lane = threadIdx.x & 31;
    int beg = g_rowptr[node], end = g_rowptr[node + 1];
    float4 aldv = *(const float4*)&ald[node * 4];

    float m0 = -1e30f, m1 = -1e30f, m2 = -1e30f, m3 = -1e30f;
    for (int j = beg + lane; j < end; j += 32) {
        int s = g_elist[j];
        float4 a = *(const float4*)&als[s * 4];
        m0 = fmaxf(m0, lrelu(a.x + aldv.x));
        m1 = fmaxf(m1, lrelu(a.y + aldv.y));
        m2 = fmaxf(m2, lrelu(a.z + aldv.z));
        m3 = fmaxf(m3, lrelu(a.w + aldv.w));
    }
#pragma unroll
    for (int o = 16; o; o >>= 1) {
        m0 = fmaxf(m0, __shfl_xor_sync(0xFFFFFFFFu, m0, o));
        m1 = fmaxf(m1, __shfl_xor_sync(0xFFFFFFFFu, m1, o));
        m2 = fmaxf(m2, __shfl_xor_sync(0xFFFFFFFFu, m2, o));
        m3 = fmaxf(m3, __shfl_xor_sync(0xFFFFFFFFu, m3, o));
    }
    float d0 = 0.f, d1 = 0.f, d2 = 0.f, d3 = 0.f;
    for (int j = beg + lane; j < end; j += 32) {
        int s = g_elist[j];
        float4 a = *(const float4*)&als[s * 4];
        float t0 = expf(lrelu(a.x + aldv.x) - m0);
        float t1 = expf(lrelu(a.y + aldv.y) - m1);
        float t2 = expf(lrelu(a.z + aldv.z) - m2);
        float t3 = expf(lrelu(a.w + aldv.w) - m3);
        *(float4*)&g_t1[(size_t)j * 4] = make_float4(t0, t1, t2, t3);
        d0 += t0; d1 += t1; d2 += t2; d3 += t3;
    }
#pragma unroll
    for (int o = 16; o; o >>= 1) {
        d0 += __shfl_xor_sync(0xFFFFFFFFu, d0, o);
        d1 += __shfl_xor_sync(0xFFFFFFFFu, d1, o);
        d2 += __shfl_xor_sync(0xFFFFFFFFu, d2, o);
        d3 += __shfl_xor_sync(0xFFFFFFFFu, d3, o);
    }
    if (lane == 0) {
        *(float4*)&g_inv1[node * 4] = make_float4(
            1.f / (d0 + 1e-16f), 1.f / (d1 + 1e-16f),
            1.f / (d2 + 1e-16f), 1.f / (d3 + 1e-16f));
    }
}

// ---------------- gather layer1: warp per node, f32x2 accumulate ----------------
__global__ void gather1(const float* __restrict__ xh, const float* __restrict__ bias,
                        float* __restrict__ hout) {
    int node = (blockIdx.x * blockDim.x + threadIdx.x) >> 5;
    if (node >= NV) return;
    int lane = threadIdx.x & 31;
    int beg = g_rowptr[node], end = g_rowptr[node + 1];
    int myh = lane >> 3;
    float myinv = g_inv1[node * 4 + myh];

    ull acc[4] = {0ull, 0ull, 0ull, 0ull};
    for (int j0 = beg; j0 < end; j0 += 32) {
        int sv = (j0 + lane < end) ? g_elist[j0 + lane] : 0;
        int cnt = min(32, end - j0);
        for (int k = 0; k < cnt; k++) {
            int s = __shfl_sync(0xFFFFFFFFu, sv, k);
            float w = g_t1[(size_t)(j0 + k) * 4 + myh] * myinv;
            ull wd; PACK2(wd, w);
            const ull* r = (const ull*)(xh + (size_t)s * 256 + lane * 8);
            FMA2(acc[0], r[0], wd);
            FMA2(acc[1], r[1], wd);
            FMA2(acc[2], r[2], wd);
            FMA2(acc[3], r[3], wd);
        }
    }
    int c = lane * 8;
    float o[8];
#pragma unroll
    for (int i = 0; i < 4; i++) {
        unsigned lo, hi;
        UNPACK2(lo, hi, acc[i]);
        float v0 = __uint_as_float(lo) + bias[c + 2 * i];
        float v1 = __uint_as_float(hi) + bias[c + 2 * i + 1];
        o[2 * i]     = v0 > 0.f ? v0 : expm1f(v0);
        o[2 * i + 1] = v1 > 0.f ? v1 : expm1f(v1);
    }
    *(float4*)(hout + (size_t)node * 256 + c)     = *(float4*)&o[0];
    *(float4*)(hout + (size_t)node * 256 + c + 4) = *(float4*)&o[4];
}

// ---------------- softmax layer2 --------------------------------------------------
__global__ void soft2(const float* __restrict__ als, const float* __restrict__ ald) {
    int node = (blockIdx.x * blockDim.x + threadIdx.x) >> 5;
    if (node >= NV) return;
    int lane = threadIdx.x & 31;
    int beg = g_rowptr[node], end = g_rowptr[node + 1];
    float aldv = ald[node];

    float m = -1e30f;
    for (int j = beg + lane; j < end; j += 32) {
        int s = g_elist[j];
        m = fmaxf(m, lrelu(als[s] + aldv));
    }
#pragma unroll
    for (int o = 16; o; o >>= 1) m = fmaxf(m, __shfl_xor_sync(0xFFFFFFFFu, m, o));

    float den = 0.f;
    for (int j = beg + lane; j < end; j += 32) {
        int s = g_elist[j];
        float t = expf(lrelu(als[s] + aldv) - m);
        g_t2[j] = t;
        den += t;
    }
#pragma unroll
    for (int o = 16; o; o >>= 1) den += __shfl_xor_sync(0xFFFFFFFFu, den, o);
    if (lane == 0) g_inv2[node] = 1.f / (den + 1e-16f);
}

// ---------------- gather layer2 ----------------------------------------------------
__global__ void gather2(const float* __restrict__ xh, const float* __restrict__ bias,
                        float* __restrict__ out) {
    int node = (blockIdx.x * blockDim.x + threadIdx.x) >> 5;
    if (node >= NV) return;
    int lane = threadIdx.x & 31;
    int beg = g_rowptr[node], end = g_rowptr[node + 1];
    float inv = g_inv2[node];

    ull acc = 0ull;
    for (int j0 = beg; j0 < end; j0 += 32) {
        int idx = j0 + lane;
        int sv = (idx < end) ? g_elist[idx] : 0;
        float tv = (idx < end) ? g_t2[idx] : 0.f;
        int cnt = min(32, end - j0);
        for (int k = 0; k < cnt; k++) {
            int s = __shfl_sync(0xFFFFFFFFu, sv, k);
            float w = __shfl_sync(0xFFFFFFFFu, tv, k) * inv;
            ull wd; PACK2(wd, w);
            ull r = *(const ull*)(xh + (size_t)s * 64 + lane * 2);
            FMA2(acc, r, wd);
        }
    }
    int c = lane * 2;
    unsigned lo, hi;
    UNPACK2(lo, hi, acc);
    float v0 = __uint_as_float(lo) + bias[c];
    float v1 = __uint_as_float(hi) + bias[c + 1];
    float r0 = v0 > 0.f ? v0 : expm1f(v0);
    float r1 = v1 > 0.f ? v1 : expm1f(v1);
    *(float2*)(out + (size_t)node * 64 + c) = make_float2(r0, r1);
}

// ---------------- launch ---------------------------------------------------------
extern "C" void kernel_launch(void* const* d_in, const int* in_sizes, int n_in,
                              void* d_out, int out_size) {
    const float* x     = (const float*)d_in[0];
    const int*   ei    = (const int*)d_in[1];
    const float* W1    = (const float*)d_in[2];
    const float* asrc1 = (const float*)d_in[3];
    const float* adst1 = (const float*)d_in[4];
    const float* b1    = (const float*)d_in[5];
    const float* W2    = (const float*)d_in[6];
    const float* asrc2 = (const float*)d_in[7];
    const float* adst2 = (const float*)d_in[8];
    const float* b2    = (const float*)d_in[9];
    float* out = (float*)d_out;

    float *xh1, *h1, *xh2, *als1, *ald1, *als2, *ald2;
    cudaGetSymbolAddress((void**)&xh1,  g_xh1);
    cudaGetSymbolAddress((void**)&h1,   g_h1);
    cudaGetSymbolAddress((void**)&xh2,  g_xh2);
    cudaGetSymbolAddress((void**)&als1, g_als1);
    cudaGetSymbolAddress((void**)&ald1, g_ald1);
    cudaGetSymbolAddress((void**)&als2, g_als2);
    cudaGetSymbolAddress((void**)&ald2, g_ald2);

    const int TB = 256;

    // ----- CSR build -----
    deg_init<<<(NV + TB - 1) / TB, TB>>>();
    deg_hist<<<(EE + TB - 1) / TB, TB>>>(ei);
    scan_k<<<1, 1024>>>();
    scatter_k<<<(ET + TB - 1) / TB, TB>>>(ei);

    // ----- layer 1 -----
    {
        dim3 grid(D1 / 128, (NV + 127) / 128);
        sgemm128<<<grid, 256>>>(x, W1, xh1, NV, D1, FIN);
    }
    attn_dots<<<(NV * HEADS * 32 + TB - 1) / TB, TB>>>(xh1, asrc1, adst1, als1, ald1, NV * HEADS, HEADS);
    soft1<<<(NV * 32 + TB - 1) / TB, TB>>>(als1, ald1);
    gather1<<<(NV * 32 + TB - 1) / TB, TB>>>(xh1, b1, h1);

    // ----- layer 2 -----
    {
        dim3 grid(1, (NV + 127) / 128);
        sgemm64<<<grid, 256>>>(h1, W2, xh2, NV, HID, D1);
    }
    attn_dots<<<(NV * 32 + TB - 1) / TB, TB>>>(xh2, asrc2, adst2, als2, ald2, NV, 1);
    soft2<<<(NV * 32 + TB - 1) / TB, TB>>>(als2, ald2);
    gather2<<<(NV * 32 + TB - 1) / TB, TB>>>(xh2, b2, out);
}

// round 6
// speedup vs baseline: 1.2604x; 1.2604x over previous
#include <cuda_runtime.h>
#include <cuda_bf16.h>
#include <math.h>
#include <cstdint>

#define NV 50000
#define EE 800000
#define ET (EE + NV)
#define HEADS 4
#define D1 256
#define KTOT 768

typedef unsigned long long ull;

// ---------------- scratch ------------------------------------------------------
__device__ float g_xh1[NV * D1];
__device__ float g_xh2[NV * 64];
__device__ __nv_bfloat16 g_xb[(size_t)NV * 512];    // x split: [hi(256)|lo(256)]
__device__ __nv_bfloat16 g_h2b[(size_t)NV * 512];   // h split: [hi(256)|lo(256)]
__device__ __nv_bfloat16 g_w1b[256 * KTOT];
__device__ __nv_bfloat16 g_w2b[64 * KTOT];
__device__ float g_als1[NV * HEADS], g_ald1[NV * HEADS];
__device__ float g_als2[NV], g_ald2[NV];
__device__ float g_inv1[NV * HEADS], g_inv2[NV];
__device__ float g_t1[(size_t)ET * HEADS];
__device__ float g_t2[ET];
__device__ int g_rowptr[NV + 1], g_deg[NV], g_elist[ET];

// ---------------- helpers ------------------------------------------------------
__device__ __forceinline__ float lrelu(float v) { return v > 0.f ? v : 0.2f * v; }
__device__ __forceinline__ void edge_sd(const int* __restrict__ ei, int e, int& s, int& d) {
    if (e < EE) { s = ei[e]; d = ei[EE + e]; } else { s = e - EE; d = s; }
}
#define FMA2(acc, a, b) asm("fma.rn.f32x2 %0, %1, %2, %3;" : "=l"(acc) : "l"(a), "l"(b), "l"(acc))
#define PACK2(o, v)     asm("mov.b64 %0, {%1, %1};" : "=l"(o) : "r"(__float_as_uint(v)))
#define UNPACK2(l, h, i) asm("mov.b64 {%0, %1}, %2;" : "=r"(l), "=r"(h) : "l"(i))

__device__ __forceinline__ uint32_t smem_u32(const void* p) {
    uint32_t a;
    asm("{ .reg .u64 t; cvta.to.shared.u64 t, %1; cvt.u32.u64 %0, t; }" : "=r"(a) : "l"(p));
    return a;
}
#define CP16(dst, src) asm volatile("cp.async.ca.shared.global [%0], [%1], 16;" :: "r"(dst), "l"(src))
#define CPCOMMIT()     asm volatile("cp.async.commit_group;" ::: "memory")
#define CPWAIT(n)      asm volatile("cp.async.wait_group %0;" :: "n"(n) : "memory")

// ---------------- conversions ----------------------------------------------------
__global__ void convW(const float* __restrict__ W, __nv_bfloat16* __restrict__ Bt, int Nc) {
    int i = blockIdx.x * blockDim.x + threadIdx.x;
    if (i >= 256 * Nc) return;
    int k = i / Nc, n = i % Nc;
    float w = W[k * Nc + n];
    __nv_bfloat16 hi = __float2bfloat16_rn(w);
    __nv_bfloat16 lo = __float2bfloat16_rn(w - __bfloat162float(hi));
    Bt[(size_t)n * KTOT + k] = hi;
    Bt[(size_t)n * KTOT + 256 + k] = hi;
    Bt[(size_t)n * KTOT + 512 + k] = lo;
}
__global__ void convX(const float* __restrict__ x, __nv_bfloat16* __restrict__ xb) {
    int i = blockIdx.x * blockDim.x + threadIdx.x;
    if (i >= NV * 64) return;
    int node = i >> 6, c = (i & 63) * 4;
    float4 f = *(const float4*)&x[(size_t)node * 256 + c];
    float ff[4] = {f.x, f.y, f.z, f.w};
    __nv_bfloat16 hb[4], lb[4];
#pragma unroll
    for (int e = 0; e < 4; e++) {
        hb[e] = __float2bfloat16_rn(ff[e]);
        lb[e] = __float2bfloat16_rn(ff[e] - __bfloat162float(hb[e]));
    }
    *(ull*)&xb[(size_t)node * 512 + c] = *(ull*)hb;
    *(ull*)&xb[(size_t)node * 512 + 256 + c] = *(ull*)lb;
}

// ---------------- CSR build --------------------------------------------------------
__global__ void deg_init() { int i = blockIdx.x * blockDim.x + threadIdx.x; if (i < NV) g_deg[i] = 1; }
__global__ void deg_hist(const int* __restrict__ ei) {
    int e = blockIdx.x * blockDim.x + threadIdx.x;
    if (e < EE) atomicAdd(&g_deg[ei[EE + e]], 1);
}
__global__ void scan_k() {
    __shared__ int ssum[1024];
    const int CH = (NV + 1023) / 1024;
    int t = threadIdx.x, base = t * CH, s = 0;
    for (int j = 0; j < CH; j++) { int i = base + j; if (i < NV) s += g_deg[i]; }
    ssum[t] = s; __syncthreads();
    for (int off = 1; off < 1024; off <<= 1) {
        int v = (t >= off) ? ssum[t - off] : 0;
        __syncthreads(); ssum[t] += v; __syncthreads();
    }
    int off = (t == 0) ? 0 : ssum[t - 1];
    for (int j = 0; j < CH; j++) {
        int i = base + j;
        if (i < NV) { int d = g_deg[i]; g_rowptr[i] = off; g_deg[i] = off; off += d; }
    }
    if (t == 0) g_rowptr[NV] = ET;
}
__global__ void scatter_k(const int* __restrict__ ei) {
    int e = blockIdx.x * blockDim.x + threadIdx.x;
    if (e >= ET) return;
    int s, d; edge_sd(ei, e, s, d);
    g_elist[atomicAdd(&g_deg[d], 1)] = s;
}

// ---------------- mma.sync bf16 GEMM + fused attention dots -------------------------
// C[M,NTOT] tile: 128(M) x 64(N) per CTA; A = Ab[M,512] (hi|lo), B = Bt[N,768] K-major.
// K = 768 in 24 stages of 32; cp.async double-buffered; 8 warps of 32x32.
template <int H>
__global__ __launch_bounds__(256) void gemm_mma(
    const __nv_bfloat16* __restrict__ Ab, const __nv_bfloat16* __restrict__ Bt,
    float* __restrict__ C, const float* __restrict__ asrc, const float* __restrict__ adst,
    float* __restrict__ als, float* __restrict__ ald, int M, int NTOT) {
    __shared__ __align__(16) __nv_bfloat16 sA[2][128 * 40];   // 80B row stride
    __shared__ __align__(16) __nv_bfloat16 sB[2][64 * 40];
    __shared__ float sdot[128][2];
    int tid = threadIdx.x, lane = tid & 31, w = tid >> 5;
    int wm = w & 3, wn = w >> 2;
    int rowBase = blockIdx.y * 128, n0 = blockIdx.x * 64;

    uint32_t sAa = smem_u32(&sA[0][0]);
    uint32_t sBa = smem_u32(&sB[0][0]);

    int arow = tid >> 1, aseg = (tid & 1) * 16;         // 16 bf16 per thread (A)
    int brow = tid >> 2, bseg = (tid & 3) * 8;          // 8 bf16 per thread (B)
    const __nv_bfloat16* Asrc = Ab + (size_t)min(rowBase + arow, M - 1) * 512 + aseg;
    const __nv_bfloat16* Bsrc = Bt + (size_t)(n0 + brow) * KTOT + bseg;
    uint32_t Adst = sAa + arow * 80 + aseg * 2;
    uint32_t Bdst = sBa + brow * 80 + bseg * 2;

#define ISSUE(s) do { \
    int _b = (s) & 1; int _k0 = (s) * 32; \
    int _ac = (_k0 < 512) ? _k0 : _k0 - 512; \
    CP16(Adst + _b * 10240, Asrc + _ac); \
    CP16(Adst + _b * 10240 + 16, Asrc + _ac + 8); \
    CP16(Bdst + _b * 5120, Bsrc + _k0); \
} while (0)

    float acc[2][4][4];
#pragma unroll
    for (int i = 0; i < 2; i++)
#pragma unroll
        for (int j = 0; j < 4; j++)
#pragma unroll
            for (int q = 0; q < 4; q++) acc[i][j][q] = 0.f;

    ISSUE(0); CPCOMMIT();
    for (int s = 0; s < 24; s++) {
        if (s < 23) { ISSUE(s + 1); CPCOMMIT(); CPWAIT(1); }
        else        { CPWAIT(0); }
        __syncthreads();
        int b = s & 1;
        uint32_t baseA = sAa + b * 10240;
        uint32_t baseB = sBa + b * 5120;
#pragma unroll
        for (int kt = 0; kt < 2; kt++) {
            uint32_t a[2][4], bb[4][2];
#pragma unroll
            for (int mt = 0; mt < 2; mt++) {
                uint32_t addr = baseA + (wm * 32 + mt * 16 + (lane & 15)) * 80 +
                                kt * 32 + (lane >> 4) * 16;
                asm volatile("ldmatrix.sync.aligned.m8n8.x4.shared.b16 {%0,%1,%2,%3}, [%4];"
                             : "=r"(a[mt][0]), "=r"(a[mt][1]), "=r"(a[mt][2]), "=r"(a[mt][3])
                             : "r"(addr));
            }
#pragma unroll
            for (int nt = 0; nt < 4; nt++) {
                uint32_t addr = baseB + (wn * 32 + nt * 8 + (lane & 7)) * 80 +
                                kt * 32 + ((lane >> 3) & 1) * 16;
                asm volatile("ldmatrix.sync.aligned.m8n8.x2.shared.b16 {%0,%1}, [%2];"
                             : "=r"(bb[nt][0]), "=r"(bb[nt][1]) : "r"(addr));
            }
#pragma unroll
            for (int mt = 0; mt < 2; mt++)
#pragma unroll
                for (int nt = 0; nt < 4; nt++)
                    asm volatile(
                        "mma.sync.aligned.m16n8k16.row.col.f32.bf16.bf16.f32 "
                        "{%0,%1,%2,%3}, {%4,%5,%6,%7}, {%8,%9}, {%0,%1,%2,%3};"
                        : "+f"(acc[mt][nt][0]), "+f"(acc[mt][nt][1]),
                          "+f"(acc[mt][nt][2]), "+f"(acc[mt][nt][3])
                        : "r"(a[mt][0]), "r"(a[mt][1]), "r"(a[mt][2]), "r"(a[mt][3]),
                          "r"(bb[nt][0]), "r"(bb[nt][1]));
        }
        __syncthreads();
    }
#undef ISSUE

    // ---------------- epilogue: C store + fused attention dots ----------------
    sdot[tid >> 1][tid & 1] = 0.f;
    __syncthreads();
    int g = lane >> 2, tg = lane & 3;
    float as_[8], ad_[8];
#pragma unroll
    for (int nt = 0; nt < 4; nt++)
#pragma unroll
        for (int j = 0; j < 2; j++) {
            int col = n0 + wn * 32 + nt * 8 + tg * 2 + j;
            as_[nt * 2 + j] = asrc[col];
            ad_[nt * 2 + j] = adst[col];
        }
#pragma unroll
    for (int mt = 0; mt < 2; mt++) {
        int r0l = wm * 32 + mt * 16 + g, r1l = r0l + 8;
        int r0 = rowBase + r0l, r1 = rowBase + r1l;
        float s0 = 0.f, d0 = 0.f, s1 = 0.f, d1 = 0.f;
#pragma unroll
        for (int nt = 0; nt < 4; nt++) {
#pragma unroll
            for (int j = 0; j < 2; j++) {
                s0 += acc[mt][nt][j] * as_[nt * 2 + j];
                d0 += acc[mt][nt][j] * ad_[nt * 2 + j];
                s1 += acc[mt][nt][2 + j] * as_[nt * 2 + j];
                d1 += acc[mt][nt][2 + j] * ad_[nt * 2 + j];
            }
            int col = n0 + wn * 32 + nt * 8 + tg * 2;
            if (r0 < M) *(float2*)&C[(size_t)r0 * NTOT + col] = make_float2(acc[mt][nt][0], acc[mt][nt][1]);
            if (r1 < M) *(float2*)&C[(size_t)r1 * NTOT + col] = make_float2(acc[mt][nt][2], acc[mt][nt][3]);
        }
#pragma unroll
        for (int o = 1; o <= 2; o <<= 1) {
            s0 += __shfl_xor_sync(~0u, s0, o); d0 += __shfl_xor_sync(~0u, d0, o);
            s1 += __shfl_xor_sync(~0u, s1, o); d1 += __shfl_xor_sync(~0u, d1, o);
        }
        if (tg == 0) {
            atomicAdd(&sdot[r0l][0], s0); atomicAdd(&sdot[r0l][1], d0);
            atomicAdd(&sdot[r1l][0], s1); atomicAdd(&sdot[r1l][1], d1);
        }
    }
    __syncthreads();
    if (tid < 128) {
        int r = rowBase + tid;
        if (r < M) {
            int head = blockIdx.x;
            als[(size_t)r * H + head] = sdot[tid][0];
            ald[(size_t)r * H + head] = sdot[tid][1];
        }
    }
}

// ---------------- softmax layer1 ---------------------------------------------------
__global__ void soft1(const float* __restrict__ als, const float* __restrict__ ald) {
    int node = (blockIdx.x * blockDim.x + threadIdx.x) >> 5;
    if (node >= NV) return;
    int lane = threadIdx.x & 31;
    int beg = g_rowptr[node], end = g_rowptr[node + 1];
    float4 av = *(const float4*)&ald[node * 4];
    float m0 = -1e30f, m1 = -1e30f, m2 = -1e30f, m3 = -1e30f;
    for (int j = beg + lane; j < end; j += 32) {
        float4 a = *(const float4*)&als[g_elist[j] * 4];
        m0 = fmaxf(m0, lrelu(a.x + av.x)); m1 = fmaxf(m1, lrelu(a.y + av.y));
        m2 = fmaxf(m2, lrelu(a.z + av.z)); m3 = fmaxf(m3, lrelu(a.w + av.w));
    }
#pragma unroll
    for (int o = 16; o; o >>= 1) {
        m0 = fmaxf(m0, __shfl_xor_sync(~0u, m0, o)); m1 = fmaxf(m1, __shfl_xor_sync(~0u, m1, o));
        m2 = fmaxf(m2, __shfl_xor_sync(~0u, m2, o)); m3 = fmaxf(m3, __shfl_xor_sync(~0u, m3, o));
    }
    float d0 = 0.f, d1 = 0.f, d2 = 0.f, d3 = 0.f;
    for (int j = beg + lane; j < end; j += 32) {
        float4 a = *(const float4*)&als[g_elist[j] * 4];
        float t0 = expf(lrelu(a.x + av.x) - m0), t1 = expf(lrelu(a.y + av.y) - m1);
        float t2 = expf(lrelu(a.z + av.z) - m2), t3 = expf(lrelu(a.w + av.w) - m3);
        *(float4*)&g_t1[(size_t)j * 4] = make_float4(t0, t1, t2, t3);
        d0 += t0; d1 += t1; d2 += t2; d3 += t3;
    }
#pragma unroll
    for (int o = 16; o; o >>= 1) {
        d0 += __shfl_xor_sync(~0u, d0, o); d1 += __shfl_xor_sync(~0u, d1, o);
        d2 += __shfl_xor_sync(~0u, d2, o); d3 += __shfl_xor_sync(~0u, d3, o);
    }
    if (lane == 0)
        *(float4*)&g_inv1[node * 4] = make_float4(1.f / (d0 + 1e-16f), 1.f / (d1 + 1e-16f),
                                                  1.f / (d2 + 1e-16f), 1.f / (d3 + 1e-16f));
}

// ---------------- gather layer1 (unrolled) + bf16 split output ----------------------
__global__ void gather1(const float* __restrict__ xh, const float* __restrict__ bias,
                        __nv_bfloat16* __restrict__ h2b) {
    int node = (blockIdx.x * blockDim.x + threadIdx.x) >> 5;
    if (node >= NV) return;
    int lane = threadIdx.x & 31;
    int beg = g_rowptr[node], end = g_rowptr[node + 1];
    int myh = lane >> 3;
    float myinv = g_inv1[node * 4 + myh];
    ull acc[4] = {0, 0, 0, 0};
    int j0 = beg;
    for (; j0 + 32 <= end; j0 += 32) {
        int sv = g_elist[j0 + lane];
#pragma unroll 8
        for (int k = 0; k < 32; k++) {
            int s = __shfl_sync(~0u, sv, k);
            float w = g_t1[(size_t)(j0 + k) * 4 + myh] * myinv;
            ull wd; PACK2(wd, w);
            const ull* rp = (const ull*)(xh + (size_t)s * 256 + lane * 8);
            FMA2(acc[0], rp[0], wd); FMA2(acc[1], rp[1], wd);
            FMA2(acc[2], rp[2], wd); FMA2(acc[3], rp[3], wd);
        }
    }
    if (j0 < end) {
        int sv = (j0 + lane < end) ? g_elist[j0 + lane] : 0;
        int cnt = end - j0;
        for (int k = 0; k < cnt; k++) {
            int s = __shfl_sync(~0u, sv, k);
            float w = g_t1[(size_t)(j0 + k) * 4 + myh] * myinv;
            ull wd; PACK2(wd, w);
            const ull* rp = (const ull*)(xh + (size_t)s * 256 + lane * 8);
            FMA2(acc[0], rp[0], wd); FMA2(acc[1], rp[1], wd);
            FMA2(acc[2], rp[2], wd); FMA2(acc[3], rp[3], wd);
        }
    }
    int c = lane * 8;
    float o[8];
#pragma unroll
    for (int i = 0; i < 4; i++) {
        unsigned lo_, hi_;
        UNPACK2(lo_, hi_, acc[i]);
        float v0 = __uint_as_float(lo_) + bias[c + 2 * i];
        float v1 = __uint_as_float(hi_) + bias[c + 2 * i + 1];
        o[2 * i] = v0 > 0.f ? v0 : expm1f(v0);
        o[2 * i + 1] = v1 > 0.f ? v1 : expm1f(v1);
    }
    __nv_bfloat16 hb[8], lb[8];
#pragma unroll
    for (int i = 0; i < 8; i++) {
        hb[i] = __float2bfloat16_rn(o[i]);
        lb[i] = __float2bfloat16_rn(o[i] - __bfloat162float(hb[i]));
    }
    *(uint4*)&h2b[(size_t)node * 512 + c] = *(uint4*)hb;
    *(uint4*)&h2b[(size_t)node * 512 + 256 + c] = *(uint4*)lb;
}

// ---------------- softmax + gather layer2 --------------------------------------------
__global__ void soft2(const float* __restrict__ als, const float* __restrict__ ald) {
    int node = (blockIdx.x * blockDim.x + threadIdx.x) >> 5;
    if (node >= NV) return;
    int lane = threadIdx.x & 31;
    int beg = g_rowptr[node], end = g_rowptr[node + 1];
    float av = ald[node];
    float m = -1e30f;
    for (int j = beg + lane; j < end; j += 32) m = fmaxf(m, lrelu(als[g_elist[j]] + av));
#pragma unroll
    for (int o = 16; o; o >>= 1) m = fmaxf(m, __shfl_xor_sync(~0u, m, o));
    float den = 0.f;
    for (int j = beg + lane; j < end; j += 32) {
        float t = expf(lrelu(als[g_elist[j]] + av) - m);
        g_t2[j] = t; den += t;
    }
#pragma unroll
    for (int o = 16; o; o >>= 1) den += __shfl_xor_sync(~0u, den, o);
    if (lane == 0) g_inv2[node] = 1.f / (den + 1e-16f);
}
__global__ void gather2(const float* __restrict__ xh, const float* __restrict__ bias,
                        float* __restrict__ out) {
    int node = (blockIdx.x * blockDim.x + threadIdx.x) >> 5;
    if (node >= NV) return;
    int lane = threadIdx.x & 31;
    int beg = g_rowptr[node], end = g_rowptr[node + 1];
    float inv = g_inv2[node];
    ull acc = 0;
    int j0 = beg;
    for (; j0 + 32 <= end; j0 += 32) {
        int sv = g_elist[j0 + lane];
        float tv = g_t2[j0 + lane];
#pragma unroll 8
        for (int k = 0; k < 32; k++) {
            int s = __shfl_sync(~0u, sv, k);
            float w = __shfl_sync(~0u, tv, k) * inv;
            ull wd; PACK2(wd, w);
            FMA2(acc, *(const ull*)(xh + (size_t)s * 64 + lane * 2), wd);
        }
    }
    if (j0 < end) {
        int sv = (j0 + lane < end) ? g_elist[j0 + lane] : 0;
        float tv = (j0 + lane < end) ? g_t2[j0 + lane] : 0.f;
        int cnt = end - j0;
        for (int k = 0; k < cnt; k++) {
            int s = __shfl_sync(~0u, sv, k);
            float w = __shfl_sync(~0u, tv, k) * inv;
            ull wd; PACK2(wd, w);
            FMA2(acc, *(const ull*)(xh + (size_t)s * 64 + lane * 2), wd);
        }
    }
    unsigned lo, hi;
    UNPACK2(lo, hi, acc);
    int c = lane * 2;
    float v0 = __uint_as_float(lo) + bias[c], v1 = __uint_as_float(hi) + bias[c + 1];
    *(float2*)(out + (size_t)node * 64 + c) =
        make_float2(v0 > 0.f ? v0 : expm1f(v0), v1 > 0.f ? v1 : expm1f(v1));
}

// ---------------- launch ---------------------------------------------------------------
extern "C" void kernel_launch(void* const* d_in, const int* in_sizes, int n_in,
                              void* d_out, int out_size) {
    const float* x     = (const float*)d_in[0];
    const int*   ei    = (const int*)d_in[1];
    const float* W1    = (const float*)d_in[2];
    const float* asrc1 = (const float*)d_in[3];
    const float* adst1 = (const float*)d_in[4];
    const float* b1    = (const float*)d_in[5];
    const float* W2    = (const float*)d_in[6];
    const float* asrc2 = (const float*)d_in[7];
    const float* adst2 = (const float*)d_in[8];
    const float* b2    = (const float*)d_in[9];
    float* out = (float*)d_out;

    float *xh1, *xh2, *als1, *ald1, *als2, *ald2;
    __nv_bfloat16 *w1b, *w2b, *xb, *h2b;
    cudaGetSymbolAddress((void**)&xh1, g_xh1);
    cudaGetSymbolAddress((void**)&xh2, g_xh2);
    cudaGetSymbolAddress((void**)&als1, g_als1);
    cudaGetSymbolAddress((void**)&ald1, g_ald1);
    cudaGetSymbolAddress((void**)&als2, g_als2);
    cudaGetSymbolAddress((void**)&ald2, g_ald2);
    cudaGetSymbolAddress((void**)&w1b, g_w1b);
    cudaGetSymbolAddress((void**)&w2b, g_w2b);
    cudaGetSymbolAddress((void**)&xb, g_xb);
    cudaGetSymbolAddress((void**)&h2b, g_h2b);

    const int TB = 256;

    // CSR + conversions
    deg_init<<<(NV + TB - 1) / TB, TB>>>();
    deg_hist<<<(EE + TB - 1) / TB, TB>>>(ei);
    scan_k<<<1, 1024>>>();
    scatter_k<<<(ET + TB - 1) / TB, TB>>>(ei);
    convW<<<(256 * 256 + TB - 1) / TB, TB>>>(W1, w1b, 256);
    convW<<<(256 * 64 + TB - 1) / TB, TB>>>(W2, w2b, 64);
    convX<<<(NV * 64 + TB - 1) / TB, TB>>>(x, xb);

    // layer 1
    gemm_mma<4><<<dim3(4, (NV + 127) / 128), 256>>>(
        xb, w1b, xh1, asrc1, adst1, als1, ald1, NV, 256);
    soft1<<<(NV * 32 + TB - 1) / TB, TB>>>(als1, ald1);
    gather1<<<(NV * 32 + TB - 1) / TB, TB>>>(xh1, b1, h2b);

    // layer 2
    gemm_mma<1><<<dim3(1, (NV + 127) / 128), 256>>>(
        h2b, w2b, xh2, asrc2, adst2, als2, ald2, NV, 64);
    soft2<<<(NV * 32 + TB - 1) / TB, TB>>>(als2, ald2);
    gather2<<<(NV * 32 + TB - 1) / TB, TB>>>(xh2, b2, out);
}

// round 7
// speedup vs baseline: 1.4517x; 1.1518x over previous
#include <cuda_runtime.h>
#include <cuda_bf16.h>
#include <math.h>
#include <cstdint>

#define NV 50000
#define EE 800000
#define ET (EE + NV)
#define HEADS 4
#define D1 256
#define KTOT 768

typedef unsigned long long ull;

// ---------------- scratch ------------------------------------------------------
__device__ float g_xh1[NV * D1];
__device__ float g_xh2[NV * 64];
__device__ __nv_bfloat16 g_xb[(size_t)NV * 512];    // x split: [hi(256)|lo(256)]
__device__ __nv_bfloat16 g_h2b[(size_t)NV * 512];   // h split: [hi(256)|lo(256)]
__device__ __nv_bfloat16 g_w1b[256 * KTOT];
__device__ __nv_bfloat16 g_w2b[64 * KTOT];
__device__ float g_als1[NV * HEADS], g_ald1[NV * HEADS];
__device__ float g_als2[NV], g_ald2[NV];
__device__ float g_t1[(size_t)ET * HEADS];
__device__ float g_t2[ET];
__device__ int g_rowptr[NV + 1], g_deg[NV], g_elist[ET];

// ---------------- helpers ------------------------------------------------------
__device__ __forceinline__ float lrelu(float v) { return v > 0.f ? v : 0.2f * v; }
__device__ __forceinline__ void edge_sd(const int* __restrict__ ei, int e, int& s, int& d) {
    if (e < EE) { s = ei[e]; d = ei[EE + e]; } else { s = e - EE; d = s; }
}
#define FMA2(acc, a, b) asm("fma.rn.f32x2 %0, %1, %2, %3;" : "=l"(acc) : "l"(a), "l"(b), "l"(acc))
#define PACK2(o, v)     asm("mov.b64 %0, {%1, %1};" : "=l"(o) : "r"(__float_as_uint(v)))
#define UNPACK2(l, h, i) asm("mov.b64 {%0, %1}, %2;" : "=r"(l), "=r"(h) : "l"(i))

__device__ __forceinline__ uint32_t smem_u32(const void* p) {
    uint32_t a;
    asm("{ .reg .u64 t; cvta.to.shared.u64 t, %1; cvt.u32.u64 %0, t; }" : "=r"(a) : "l"(p));
    return a;
}
#define CP16(dst, src) asm volatile("cp.async.ca.shared.global [%0], [%1], 16;" :: "r"(dst), "l"(src))
#define CPCOMMIT()     asm volatile("cp.async.commit_group;" ::: "memory")
#define CPWAIT(n)      asm volatile("cp.async.wait_group %0;" :: "n"(n) : "memory")

// ---------------- conversions ----------------------------------------------------
__global__ void convW(const float* __restrict__ W, __nv_bfloat16* __restrict__ Bt, int Nc) {
    int i = blockIdx.x * blockDim.x + threadIdx.x;
    if (i >= 256 * Nc) return;
    int k = i / Nc, n = i % Nc;
    float w = W[k * Nc + n];
    __nv_bfloat16 hi = __float2bfloat16_rn(w);
    __nv_bfloat16 lo = __float2bfloat16_rn(w - __bfloat162float(hi));
    Bt[(size_t)n * KTOT + k] = hi;
    Bt[(size_t)n * KTOT + 256 + k] = hi;
    Bt[(size_t)n * KTOT + 512 + k] = lo;
}
__global__ void convX(const float* __restrict__ x, __nv_bfloat16* __restrict__ xb) {
    int i = blockIdx.x * blockDim.x + threadIdx.x;
    if (i >= NV * 64) return;
    int node = i >> 6, c = (i & 63) * 4;
    float4 f = *(const float4*)&x[(size_t)node * 256 + c];
    float ff[4] = {f.x, f.y, f.z, f.w};
    __nv_bfloat16 hb[4], lb[4];
#pragma unroll
    for (int e = 0; e < 4; e++) {
        hb[e] = __float2bfloat16_rn(ff[e]);
        lb[e] = __float2bfloat16_rn(ff[e] - __bfloat162float(hb[e]));
    }
    *(ull*)&xb[(size_t)node * 512 + c] = *(ull*)hb;
    *(ull*)&xb[(size_t)node * 512 + 256 + c] = *(ull*)lb;
}

// ---------------- CSR build --------------------------------------------------------
__global__ void deg_init() { int i = blockIdx.x * blockDim.x + threadIdx.x; if (i < NV) g_deg[i] = 1; }
__global__ void deg_hist(const int* __restrict__ ei) {
    int e = blockIdx.x * blockDim.x + threadIdx.x;
    if (e < EE) atomicAdd(&g_deg[ei[EE + e]], 1);
}
__global__ void scan_k() {
    __shared__ int ssum[1024];
    const int CH = (NV + 1023) / 1024;
    int t = threadIdx.x, base = t * CH, s = 0;
    for (int j = 0; j < CH; j++) { int i = base + j; if (i < NV) s += g_deg[i]; }
    ssum[t] = s; __syncthreads();
    for (int off = 1; off < 1024; off <<= 1) {
        int v = (t >= off) ? ssum[t - off] : 0;
        __syncthreads(); ssum[t] += v; __syncthreads();
    }
    int off = (t == 0) ? 0 : ssum[t - 1];
    for (int j = 0; j < CH; j++) {
        int i = base + j;
        if (i < NV) { int d = g_deg[i]; g_rowptr[i] = off; g_deg[i] = off; off += d; }
    }
    if (t == 0) g_rowptr[NV] = ET;
}
__global__ void scatter_k(const int* __restrict__ ei) {
    int e = blockIdx.x * blockDim.x + threadIdx.x;
    if (e >= ET) return;
    int s, d; edge_sd(ei, e, s, d);
    g_elist[atomicAdd(&g_deg[d], 1)] = s;
}

// ---------------- mma.sync bf16 GEMM + fused attention dots -------------------------
template <int H>
__global__ __launch_bounds__(256) void gemm_mma(
    const __nv_bfloat16* __restrict__ Ab, const __nv_bfloat16* __restrict__ Bt,
    float* __restrict__ C, const float* __restrict__ asrc, const float* __restrict__ adst,
    float* __restrict__ als, float* __restrict__ ald, int M, int NTOT) {
    __shared__ __align__(16) __nv_bfloat16 sA[2][128 * 40];
    __shared__ __align__(16) __nv_bfloat16 sB[2][64 * 40];
    __shared__ float sdot[128][2];
    int tid = threadIdx.x, lane = tid & 31, w = tid >> 5;
    int wm = w & 3, wn = w >> 2;
    int rowBase = blockIdx.y * 128, n0 = blockIdx.x * 64;

    uint32_t sAa = smem_u32(&sA[0][0]);
    uint32_t sBa = smem_u32(&sB[0][0]);

    int arow = tid >> 1, aseg = (tid & 1) * 16;
    int brow = tid >> 2, bseg = (tid & 3) * 8;
    const __nv_bfloat16* Asrc = Ab + (size_t)min(rowBase + arow, M - 1) * 512 + aseg;
    const __nv_bfloat16* Bsrc = Bt + (size_t)(n0 + brow) * KTOT + bseg;
    uint32_t Adst = sAa + arow * 80 + aseg * 2;
    uint32_t Bdst = sBa + brow * 80 + bseg * 2;

#define ISSUE(s) do { \
    int _b = (s) & 1; int _k0 = (s) * 32; \
    int _ac = (_k0 < 512) ? _k0 : _k0 - 512; \
    CP16(Adst + _b * 10240, Asrc + _ac); \
    CP16(Adst + _b * 10240 + 16, Asrc + _ac + 8); \
    CP16(Bdst + _b * 5120, Bsrc + _k0); \
} while (0)

    float acc[2][4][4];
#pragma unroll
    for (int i = 0; i < 2; i++)
#pragma unroll
        for (int j = 0; j < 4; j++)
#pragma unroll
            for (int q = 0; q < 4; q++) acc[i][j][q] = 0.f;

    ISSUE(0); CPCOMMIT();
    for (int s = 0; s < 24; s++) {
        if (s < 23) { ISSUE(s + 1); CPCOMMIT(); CPWAIT(1); }
        else        { CPWAIT(0); }
        __syncthreads();
        int b = s & 1;
        uint32_t baseA = sAa + b * 10240;
        uint32_t baseB = sBa + b * 5120;
#pragma unroll
        for (int kt = 0; kt < 2; kt++) {
            uint32_t a[2][4], bb[4][2];
#pragma unroll
            for (int mt = 0; mt < 2; mt++) {
                uint32_t addr = baseA + (wm * 32 + mt * 16 + (lane & 15)) * 80 +
                                kt * 32 + (lane >> 4) * 16;
                asm volatile("ldmatrix.sync.aligned.m8n8.x4.shared.b16 {%0,%1,%2,%3}, [%4];"
                             : "=r"(a[mt][0]), "=r"(a[mt][1]), "=r"(a[mt][2]), "=r"(a[mt][3])
                             : "r"(addr));
            }
#pragma unroll
            for (int nt = 0; nt < 4; nt++) {
                uint32_t addr = baseB + (wn * 32 + nt * 8 + (lane & 7)) * 80 +
                                kt * 32 + ((lane >> 3) & 1) * 16;
                asm volatile("ldmatrix.sync.aligned.m8n8.x2.shared.b16 {%0,%1}, [%2];"
                             : "=r"(bb[nt][0]), "=r"(bb[nt][1]) : "r"(addr));
            }
#pragma unroll
            for (int mt = 0; mt < 2; mt++)
#pragma unroll
                for (int nt = 0; nt < 4; nt++)
                    asm volatile(
                        "mma.sync.aligned.m16n8k16.row.col.f32.bf16.bf16.f32 "
                        "{%0,%1,%2,%3}, {%4,%5,%6,%7}, {%8,%9}, {%0,%1,%2,%3};"
                        : "+f"(acc[mt][nt][0]), "+f"(acc[mt][nt][1]),
                          "+f"(acc[mt][nt][2]), "+f"(acc[mt][nt][3])
                        : "r"(a[mt][0]), "r"(a[mt][1]), "r"(a[mt][2]), "r"(a[mt][3]),
                          "r"(bb[nt][0]), "r"(bb[nt][1]));
        }
        __syncthreads();
    }
#undef ISSUE

    sdot[tid >> 1][tid & 1] = 0.f;
    __syncthreads();
    int g = lane >> 2, tg = lane & 3;
    float as_[8], ad_[8];
#pragma unroll
    for (int nt = 0; nt < 4; nt++)
#pragma unroll
        for (int j = 0; j < 2; j++) {
            int col = n0 + wn * 32 + nt * 8 + tg * 2 + j;
            as_[nt * 2 + j] = asrc[col];
            ad_[nt * 2 + j] = adst[col];
        }
#pragma unroll
    for (int mt = 0; mt < 2; mt++) {
        int r0l = wm * 32 + mt * 16 + g, r1l = r0l + 8;
        int r0 = rowBase + r0l, r1 = rowBase + r1l;
        float s0 = 0.f, d0 = 0.f, s1 = 0.f, d1 = 0.f;
#pragma unroll
        for (int nt = 0; nt < 4; nt++) {
#pragma unroll
            for (int j = 0; j < 2; j++) {
                s0 += acc[mt][nt][j] * as_[nt * 2 + j];
                d0 += acc[mt][nt][j] * ad_[nt * 2 + j];
                s1 += acc[mt][nt][2 + j] * as_[nt * 2 + j];
                d1 += acc[mt][nt][2 + j] * ad_[nt * 2 + j];
            }
            int col = n0 + wn * 32 + nt * 8 + tg * 2;
            if (r0 < M) *(float2*)&C[(size_t)r0 * NTOT + col] = make_float2(acc[mt][nt][0], acc[mt][nt][1]);
            if (r1 < M) *(float2*)&C[(size_t)r1 * NTOT + col] = make_float2(acc[mt][nt][2], acc[mt][nt][3]);
        }
#pragma unroll
        for (int o = 1; o <= 2; o <<= 1) {
            s0 += __shfl_xor_sync(~0u, s0, o); d0 += __shfl_xor_sync(~0u, d0, o);
            s1 += __shfl_xor_sync(~0u, s1, o); d1 += __shfl_xor_sync(~0u, d1, o);
        }
        if (tg == 0) {
            atomicAdd(&sdot[r0l][0], s0); atomicAdd(&sdot[r0l][1], d0);
            atomicAdd(&sdot[r1l][0], s1); atomicAdd(&sdot[r1l][1], d1);
        }
    }
    __syncthreads();
    if (tid < 128) {
        int r = rowBase + tid;
        if (r < M) {
            int head = blockIdx.x;
            als[(size_t)r * H + head] = sdot[tid][0];
            ald[(size_t)r * H + head] = sdot[tid][1];
        }
    }
}

// ---------------- fused softmax+gather layer1 ---------------------------------------
__global__ void gat_agg1(const float* __restrict__ xh, const float* __restrict__ als,
                         const float* __restrict__ ald, const float* __restrict__ bias,
                         __nv_bfloat16* __restrict__ h2b) {
    int node = (blockIdx.x * blockDim.x + threadIdx.x) >> 5;
    if (node >= NV) return;
    int lane = threadIdx.x & 31;
    int beg = g_rowptr[node], end = g_rowptr[node + 1];
    float4 av = *(const float4*)&ald[node * 4];

    // phase 1: t = exp(lrelu(als+ald)) (no max shift needed; |e| << 88), den
    float d0 = 0.f, d1 = 0.f, d2 = 0.f, d3 = 0.f;
    for (int j = beg + lane; j < end; j += 32) {
        float4 a = *(const float4*)&als[g_elist[j] * 4];
        float t0 = __expf(lrelu(a.x + av.x)), t1 = __expf(lrelu(a.y + av.y));
        float t2 = __expf(lrelu(a.z + av.z)), t3 = __expf(lrelu(a.w + av.w));
        *(float4*)&g_t1[(size_t)j * 4] = make_float4(t0, t1, t2, t3);
        d0 += t0; d1 += t1; d2 += t2; d3 += t3;
    }
#pragma unroll
    for (int o = 16; o; o >>= 1) {
        d0 += __shfl_xor_sync(~0u, d0, o); d1 += __shfl_xor_sync(~0u, d1, o);
        d2 += __shfl_xor_sync(~0u, d2, o); d3 += __shfl_xor_sync(~0u, d3, o);
    }
    int myh = lane >> 3;
    float myinv = 1.f / ((myh == 0 ? d0 : myh == 1 ? d1 : myh == 2 ? d2 : d3) + 1e-16f);
    __syncwarp();

    // phase 2: unnormalized weighted gather
    ull acc[4] = {0, 0, 0, 0};
    int j0 = beg;
    for (; j0 + 32 <= end; j0 += 32) {
        int sv = g_elist[j0 + lane];
#pragma unroll 8
        for (int k = 0; k < 32; k++) {
            int s = __shfl_sync(~0u, sv, k);
            float t = g_t1[(size_t)(j0 + k) * 4 + myh];
            ull wd; PACK2(wd, t);
            const ull* rp = (const ull*)(xh + (size_t)s * 256 + lane * 8);
            FMA2(acc[0], rp[0], wd); FMA2(acc[1], rp[1], wd);
            FMA2(acc[2], rp[2], wd); FMA2(acc[3], rp[3], wd);
        }
    }
    if (j0 < end) {
        int sv = (j0 + lane < end) ? g_elist[j0 + lane] : 0;
        int cnt = end - j0;
        for (int k = 0; k < cnt; k++) {
            int s = __shfl_sync(~0u, sv, k);
            float t = g_t1[(size_t)(j0 + k) * 4 + myh];
            ull wd; PACK2(wd, t);
            const ull* rp = (const ull*)(xh + (size_t)s * 256 + lane * 8);
            FMA2(acc[0], rp[0], wd); FMA2(acc[1], rp[1], wd);
            FMA2(acc[2], rp[2], wd); FMA2(acc[3], rp[3], wd);
        }
    }
    // epilogue: scale by inv, +bias, ELU, bf16 hi/lo split store
    int c = lane * 8;
    float o[8];
#pragma unroll
    for (int i = 0; i < 4; i++) {
        unsigned lo_, hi_;
        UNPACK2(lo_, hi_, acc[i]);
        float v0 = __uint_as_float(lo_) * myinv + bias[c + 2 * i];
        float v1 = __uint_as_float(hi_) * myinv + bias[c + 2 * i + 1];
        o[2 * i] = v0 > 0.f ? v0 : expm1f(v0);
        o[2 * i + 1] = v1 > 0.f ? v1 : expm1f(v1);
    }
    __nv_bfloat16 hb[8], lb[8];
#pragma unroll
    for (int i = 0; i < 8; i++) {
        hb[i] = __float2bfloat16_rn(o[i]);
        lb[i] = __float2bfloat16_rn(o[i] - __bfloat162float(hb[i]));
    }
    *(uint4*)&h2b[(size_t)node * 512 + c] = *(uint4*)hb;
    *(uint4*)&h2b[(size_t)node * 512 + 256 + c] = *(uint4*)lb;
}

// ---------------- fused softmax+gather layer2 ---------------------------------------
__global__ void gat_agg2(const float* __restrict__ xh, const float* __restrict__ als,
                         const float* __restrict__ ald, const float* __restrict__ bias,
                         float* __restrict__ out) {
    int node = (blockIdx.x * blockDim.x + threadIdx.x) >> 5;
    if (node >= NV) return;
    int lane = threadIdx.x & 31;
    int beg = g_rowptr[node], end = g_rowptr[node + 1];
    float av = ald[node];

    float den = 0.f;
    for (int j = beg + lane; j < end; j += 32) {
        float t = __expf(lrelu(als[g_elist[j]] + av));
        g_t2[j] = t; den += t;
    }
#pragma unroll
    for (int o = 16; o; o >>= 1) den += __shfl_xor_sync(~0u, den, o);
    float inv = 1.f / (den + 1e-16f);
    __syncwarp();

    ull acc = 0;
    int j0 = beg;
    for (; j0 + 32 <= end; j0 += 32) {
        int sv = g_elist[j0 + lane];
        float tv = g_t2[j0 + lane];
#pragma unroll 8
        for (int k = 0; k < 32; k++) {
            int s = __shfl_sync(~0u, sv, k);
            float t = __shfl_sync(~0u, tv, k);
            ull wd; PACK2(wd, t);
            FMA2(acc, *(const ull*)(xh + (size_t)s * 64 + lane * 2), wd);
        }
    }
    if (j0 < end) {
        int sv = (j0 + lane < end) ? g_elist[j0 + lane] : 0;
        float tv = (j0 + lane < end) ? g_t2[j0 + lane] : 0.f;
        int cnt = end - j0;
        for (int k = 0; k < cnt; k++) {
            int s = __shfl_sync(~0u, sv, k);
            float t = __shfl_sync(~0u, tv, k);
            ull wd; PACK2(wd, t);
            FMA2(acc, *(const ull*)(xh + (size_t)s * 64 + lane * 2), wd);
        }
    }
    unsigned lo, hi;
    UNPACK2(lo, hi, acc);
    int c = lane * 2;
    float v0 = __uint_as_float(lo) * inv + bias[c];
    float v1 = __uint_as_float(hi) * inv + bias[c + 1];
    *(float2*)(out + (size_t)node * 64 + c) =
        make_float2(v0 > 0.f ? v0 : expm1f(v0), v1 > 0.f ? v1 : expm1f(v1));
}

// ---------------- launch ---------------------------------------------------------------
extern "C" void kernel_launch(void* const* d_in, const int* in_sizes, int n_in,
                              void* d_out, int out_size) {
    const float* x     = (const float*)d_in[0];
    const int*   ei    = (const int*)d_in[1];
    const float* W1    = (const float*)d_in[2];
    const float* asrc1 = (const float*)d_in[3];
    const float* adst1 = (const float*)d_in[4];
    const float* b1    = (const float*)d_in[5];
    const float* W2    = (const float*)d_in[6];
    const float* asrc2 = (const float*)d_in[7];
    const float* adst2 = (const float*)d_in[8];
    const float* b2    = (const float*)d_in[9];
    float* out = (float*)d_out;

    float *xh1, *xh2, *als1, *ald1, *als2, *ald2;
    __nv_bfloat16 *w1b, *w2b, *xb, *h2b;
    cudaGetSymbolAddress((void**)&xh1, g_xh1);
    cudaGetSymbolAddress((void**)&xh2, g_xh2);
    cudaGetSymbolAddress((void**)&als1, g_als1);
    cudaGetSymbolAddress((void**)&ald1, g_ald1);
    cudaGetSymbolAddress((void**)&als2, g_als2);
    cudaGetSymbolAddress((void**)&ald2, g_ald2);
    cudaGetSymbolAddress((void**)&w1b, g_w1b);
    cudaGetSymbolAddress((void**)&w2b, g_w2b);
    cudaGetSymbolAddress((void**)&xb, g_xb);
    cudaGetSymbolAddress((void**)&h2b, g_h2b);

    // Side stream + events: created on first (uncaptured) call, reused in capture.
    static cudaStream_t sCsr = nullptr;
    static cudaEvent_t ev0 = nullptr, ev1 = nullptr;
    if (!sCsr) {
        cudaStreamCreateWithFlags(&sCsr, cudaStreamNonBlocking);
        cudaEventCreateWithFlags(&ev0, cudaEventDisableTiming);
        cudaEventCreateWithFlags(&ev1, cudaEventDisableTiming);
    }

    const int TB = 256;

    // ---- fork: CSR build on side stream (independent of GEMM1 chain) ----
    cudaEventRecord(ev0, 0);
    cudaStreamWaitEvent(sCsr, ev0, 0);
    deg_init<<<(NV + TB - 1) / TB, TB, 0, sCsr>>>();
    deg_hist<<<(EE + TB - 1) / TB, TB, 0, sCsr>>>(ei);
    scan_k<<<1, 1024, 0, sCsr>>>();
    scatter_k<<<(ET + TB - 1) / TB, TB, 0, sCsr>>>(ei);
    cudaEventRecord(ev1, sCsr);

    // ---- main chain ----
    convW<<<(256 * 256 + TB - 1) / TB, TB>>>(W1, w1b, 256);
    convW<<<(256 * 64 + TB - 1) / TB, TB>>>(W2, w2b, 64);
    convX<<<(NV * 64 + TB - 1) / TB, TB>>>(x, xb);

    gemm_mma<4><<<dim3(4, (NV + 127) / 128), 256>>>(
        xb, w1b, xh1, asrc1, adst1, als1, ald1, NV, 256);

    cudaStreamWaitEvent(0, ev1, 0);   // join: aggregation needs the CSR
    gat_agg1<<<(NV * 32 + TB - 1) / TB, TB>>>(xh1, als1, ald1, b1, h2b);

    gemm_mma<1><<<dim3(1, (NV + 127) / 128), 256>>>(
        h2b, w2b, xh2, asrc2, adst2, als2, ald2, NV, 64);
    gat_agg2<<<(NV * 32 + TB - 1) / TB, TB>>>(xh2, als2, ald2, b2, out);
}

// round 8
// speedup vs baseline: 1.8599x; 1.2812x over previous
#include <cuda_runtime.h>
#include <cuda_bf16.h>
#include <math.h>
#include <cstdint>

#define NV 50000
#define EE 800000
#define ET (EE + NV)
#define HEADS 4
#define D1 256
#define KTOT 768

typedef unsigned long long ull;

// ---------------- scratch ------------------------------------------------------
__device__ float g_xh1[NV * D1];
__device__ float g_xh2[NV * 64];
__device__ __nv_bfloat16 g_xb[(size_t)NV * 512];
__device__ __nv_bfloat16 g_h2b[(size_t)NV * 512];
__device__ __nv_bfloat16 g_w1b[256 * KTOT];
__device__ __nv_bfloat16 g_w2b[64 * KTOT];
__device__ float g_als1[NV * HEADS], g_ald1[NV * HEADS];
__device__ float g_als2[NV], g_ald2[NV];
__device__ float g_t1[(size_t)ET * HEADS];
__device__ float g_t2[ET];
__device__ int g_rowptr[NV + 1], g_deg[NV], g_elist[ET];

// ---------------- helpers ------------------------------------------------------
__device__ __forceinline__ float lrelu(float v) { return v > 0.f ? v : 0.2f * v; }
__device__ __forceinline__ void edge_sd(const int* __restrict__ ei, int e, int& s, int& d) {
    if (e < EE) { s = ei[e]; d = ei[EE + e]; } else { s = e - EE; d = s; }
}
#define FMA2(acc, a, b) asm("fma.rn.f32x2 %0, %1, %2, %3;" : "=l"(acc) : "l"(a), "l"(b), "l"(acc))
#define PACK2(o, v)     asm("mov.b64 %0, {%1, %1};" : "=l"(o) : "r"(__float_as_uint(v)))
#define UNPACK2(l, h, i) asm("mov.b64 {%0, %1}, %2;" : "=r"(l), "=r"(h) : "l"(i))

__device__ __forceinline__ uint32_t smem_u32(const void* p) {
    uint32_t a;
    asm("{ .reg .u64 t; cvta.to.shared.u64 t, %1; cvt.u32.u64 %0, t; }" : "=r"(a) : "l"(p));
    return a;
}
#define CP16(dst, src) asm volatile("cp.async.ca.shared.global [%0], [%1], 16;" :: "r"(dst), "l"(src))
#define CPCOMMIT()     asm volatile("cp.async.commit_group;" ::: "memory")
#define CPWAIT(n)      asm volatile("cp.async.wait_group %0;" :: "n"(n) : "memory")

// ---------------- conversions ----------------------------------------------------
__global__ void convW(const float* __restrict__ W, __nv_bfloat16* __restrict__ Bt, int Nc) {
    int i = blockIdx.x * blockDim.x + threadIdx.x;
    if (i >= 256 * Nc) return;
    int k = i / Nc, n = i % Nc;
    float w = W[k * Nc + n];
    __nv_bfloat16 hi = __float2bfloat16_rn(w);
    __nv_bfloat16 lo = __float2bfloat16_rn(w - __bfloat162float(hi));
    Bt[(size_t)n * KTOT + k] = hi;
    Bt[(size_t)n * KTOT + 256 + k] = hi;
    Bt[(size_t)n * KTOT + 512 + k] = lo;
}
__global__ void convX(const float* __restrict__ x, __nv_bfloat16* __restrict__ xb) {
    int i = blockIdx.x * blockDim.x + threadIdx.x;
    if (i >= NV * 64) return;
    int node = i >> 6, c = (i & 63) * 4;
    float4 f = *(const float4*)&x[(size_t)node * 256 + c];
    float ff[4] = {f.x, f.y, f.z, f.w};
    __nv_bfloat16 hb[4], lb[4];
#pragma unroll
    for (int e = 0; e < 4; e++) {
        hb[e] = __float2bfloat16_rn(ff[e]);
        lb[e] = __float2bfloat16_rn(ff[e] - __bfloat162float(hb[e]));
    }
    *(ull*)&xb[(size_t)node * 512 + c] = *(ull*)hb;
    *(ull*)&xb[(size_t)node * 512 + 256 + c] = *(ull*)lb;
}

// ---------------- CSR build --------------------------------------------------------
__global__ void deg_init() { int i = blockIdx.x * blockDim.x + threadIdx.x; if (i < NV) g_deg[i] = 1; }
__global__ void deg_hist(const int* __restrict__ ei) {
    int e = blockIdx.x * blockDim.x + threadIdx.x;
    if (e < EE) atomicAdd(&g_deg[ei[EE + e]], 1);
}
__global__ void scan_k() {
    __shared__ int ssum[1024];
    const int CH = (NV + 1023) / 1024;
    int t = threadIdx.x, base = t * CH, s = 0;
    for (int j = 0; j < CH; j++) { int i = base + j; if (i < NV) s += g_deg[i]; }
    ssum[t] = s; __syncthreads();
    for (int off = 1; off < 1024; off <<= 1) {
        int v = (t >= off) ? ssum[t - off] : 0;
        __syncthreads(); ssum[t] += v; __syncthreads();
    }
    int off = (t == 0) ? 0 : ssum[t - 1];
    for (int j = 0; j < CH; j++) {
        int i = base + j;
        if (i < NV) { int d = g_deg[i]; g_rowptr[i] = off; g_deg[i] = off; off += d; }
    }
    if (t == 0) g_rowptr[NV] = ET;
}
__global__ void scatter_k(const int* __restrict__ ei) {
    int e = blockIdx.x * blockDim.x + threadIdx.x;
    if (e >= ET) return;
    int s, d; edge_sd(ei, e, s, d);
    g_elist[atomicAdd(&g_deg[d], 1)] = s;
}

// ---------------- mma.sync bf16 GEMM + fused attention dots -------------------------
template <int H>
__global__ __launch_bounds__(256) void gemm_mma(
    const __nv_bfloat16* __restrict__ Ab, const __nv_bfloat16* __restrict__ Bt,
    float* __restrict__ C, const float* __restrict__ asrc, const float* __restrict__ adst,
    float* __restrict__ als, float* __restrict__ ald, int M, int NTOT) {
    __shared__ __align__(16) __nv_bfloat16 sA[2][128 * 40];
    __shared__ __align__(16) __nv_bfloat16 sB[2][64 * 40];
    __shared__ float sdot[128][2];
    int tid = threadIdx.x, lane = tid & 31, w = tid >> 5;
    int wm = w & 3, wn = w >> 2;
    int rowBase = blockIdx.y * 128, n0 = blockIdx.x * 64;

    uint32_t sAa = smem_u32(&sA[0][0]);
    uint32_t sBa = smem_u32(&sB[0][0]);

    int arow = tid >> 1, aseg = (tid & 1) * 16;
    int brow = tid >> 2, bseg = (tid & 3) * 8;
    const __nv_bfloat16* Asrc = Ab + (size_t)min(rowBase + arow, M - 1) * 512 + aseg;
    const __nv_bfloat16* Bsrc = Bt + (size_t)(n0 + brow) * KTOT + bseg;
    uint32_t Adst = sAa + arow * 80 + aseg * 2;
    uint32_t Bdst = sBa + brow * 80 + bseg * 2;

#define ISSUE(s) do { \
    int _b = (s) & 1; int _k0 = (s) * 32; \
    int _ac = (_k0 < 512) ? _k0 : _k0 - 512; \
    CP16(Adst + _b * 10240, Asrc + _ac); \
    CP16(Adst + _b * 10240 + 16, Asrc + _ac + 8); \
    CP16(Bdst + _b * 5120, Bsrc + _k0); \
} while (0)

    float acc[2][4][4];
#pragma unroll
    for (int i = 0; i < 2; i++)
#pragma unroll
        for (int j = 0; j < 4; j++)
#pragma unroll
            for (int q = 0; q < 4; q++) acc[i][j][q] = 0.f;

    ISSUE(0); CPCOMMIT();
    for (int s = 0; s < 24; s++) {
        if (s < 23) { ISSUE(s + 1); CPCOMMIT(); CPWAIT(1); }
        else        { CPWAIT(0); }
        __syncthreads();
        int b = s & 1;
        uint32_t baseA = sAa + b * 10240;
        uint32_t baseB = sBa + b * 5120;
#pragma unroll
        for (int kt = 0; kt < 2; kt++) {
            uint32_t a[2][4], bb[4][2];
#pragma unroll
            for (int mt = 0; mt < 2; mt++) {
                uint32_t addr = baseA + (wm * 32 + mt * 16 + (lane & 15)) * 80 +
                                kt * 32 + (lane >> 4) * 16;
                asm volatile("ldmatrix.sync.aligned.m8n8.x4.shared.b16 {%0,%1,%2,%3}, [%4];"
                             : "=r"(a[mt][0]), "=r"(a[mt][1]), "=r"(a[mt][2]), "=r"(a[mt][3])
                             : "r"(addr));
            }
#pragma unroll
            for (int nt = 0; nt < 4; nt++) {
                uint32_t addr = baseB + (wn * 32 + nt * 8 + (lane & 7)) * 80 +
                                kt * 32 + ((lane >> 3) & 1) * 16;
                asm volatile("ldmatrix.sync.aligned.m8n8.x2.shared.b16 {%0,%1}, [%2];"
                             : "=r"(bb[nt][0]), "=r"(bb[nt][1]) : "r"(addr));
            }
#pragma unroll
            for (int mt = 0; mt < 2; mt++)
#pragma unroll
                for (int nt = 0; nt < 4; nt++)
                    asm volatile(
                        "mma.sync.aligned.m16n8k16.row.col.f32.bf16.bf16.f32 "
                        "{%0,%1,%2,%3}, {%4,%5,%6,%7}, {%8,%9}, {%0,%1,%2,%3};"
                        : "+f"(acc[mt][nt][0]), "+f"(acc[mt][nt][1]),
                          "+f"(acc[mt][nt][2]), "+f"(acc[mt][nt][3])
                        : "r"(a[mt][0]), "r"(a[mt][1]), "r"(a[mt][2]), "r"(a[mt][3]),
                          "r"(bb[nt][0]), "r"(bb[nt][1]));
        }
        __syncthreads();
    }
#undef ISSUE

    sdot[tid >> 1][tid & 1] = 0.f;
    __syncthreads();
    int g = lane >> 2, tg = lane & 3;
    float as_[8], ad_[8];
#pragma unroll
    for (int nt = 0; nt < 4; nt++)
#pragma unroll
        for (int j = 0; j < 2; j++) {
            int col = n0 + wn * 32 + nt * 8 + tg * 2 + j;
            as_[nt * 2 + j] = asrc[col];
            ad_[nt * 2 + j] = adst[col];
        }
#pragma unroll
    for (int mt = 0; mt < 2; mt++) {
        int r0l = wm * 32 + mt * 16 + g, r1l = r0l + 8;
        int r0 = rowBase + r0l, r1 = rowBase + r1l;
        float s0 = 0.f, d0 = 0.f, s1 = 0.f, d1 = 0.f;
#pragma unroll
        for (int nt = 0; nt < 4; nt++) {
#pragma unroll
            for (int j = 0; j < 2; j++) {
                s0 += acc[mt][nt][j] * as_[nt * 2 + j];
                d0 += acc[mt][nt][j] * ad_[nt * 2 + j];
                s1 += acc[mt][nt][2 + j] * as_[nt * 2 + j];
                d1 += acc[mt][nt][2 + j] * ad_[nt * 2 + j];
            }
            int col = n0 + wn * 32 + nt * 8 + tg * 2;
            if (r0 < M) *(float2*)&C[(size_t)r0 * NTOT + col] = make_float2(acc[mt][nt][0], acc[mt][nt][1]);
            if (r1 < M) *(float2*)&C[(size_t)r1 * NTOT + col] = make_float2(acc[mt][nt][2], acc[mt][nt][3]);
        }
#pragma unroll
        for (int o = 1; o <= 2; o <<= 1) {
            s0 += __shfl_xor_sync(~0u, s0, o); d0 += __shfl_xor_sync(~0u, d0, o);
            s1 += __shfl_xor_sync(~0u, s1, o); d1 += __shfl_xor_sync(~0u, d1, o);
        }
        if (tg == 0) {
            atomicAdd(&sdot[r0l][0], s0); atomicAdd(&sdot[r0l][1], d0);
            atomicAdd(&sdot[r1l][0], s1); atomicAdd(&sdot[r1l][1], d1);
        }
    }
    __syncthreads();
    if (tid < 128) {
        int r = rowBase + tid;
        if (r < M) {
            int head = blockIdx.x;
            als[(size_t)r * H + head] = sdot[tid][0];
            ald[(size_t)r * H + head] = sdot[tid][1];
        }
    }
}

// ---------------- fused softmax+gather layer1: 2 warps per node ---------------------
__global__ void gat_agg1(const float* __restrict__ xh, const float* __restrict__ als,
                         const float* __restrict__ ald, const float* __restrict__ bias,
                         __nv_bfloat16* __restrict__ h2b) {
    int gw = (blockIdx.x * blockDim.x + threadIdx.x) >> 5;
    int node = gw >> 1, hp = gw & 1;       // head pair: heads {2hp, 2hp+1}, cols hp*128..+127
    if (node >= NV) return;
    int lane = threadIdx.x & 31;
    int beg = g_rowptr[node], end = g_rowptr[node + 1];
    float2 av = *(const float2*)&ald[node * 4 + 2 * hp];

    // phase 1: t for this warp's two heads + denominators
    float d0 = 0.f, d1 = 0.f;
    for (int j = beg + lane; j < end; j += 32) {
        float2 a = *(const float2*)&als[g_elist[j] * 4 + 2 * hp];
        float t0 = __expf(lrelu(a.x + av.x)), t1 = __expf(lrelu(a.y + av.y));
        *(float2*)&g_t1[(size_t)j * 4 + 2 * hp] = make_float2(t0, t1);
        d0 += t0; d1 += t1;
    }
#pragma unroll
    for (int o = 16; o; o >>= 1) {
        d0 += __shfl_xor_sync(~0u, d0, o);
        d1 += __shfl_xor_sync(~0u, d1, o);
    }
    int hl = lane >> 4;                     // 0/1 within pair
    int myhead = hp * 2 + hl;
    float myinv = 1.f / ((hl ? d1 : d0) + 1e-16f);
    __syncwarp();

    // phase 2: gather (lane covers 4 floats = one LDG.128 per edge)
    int c0 = hp * 128 + lane * 4;
    ull acc[2] = {0, 0};
    int j0 = beg;
    for (; j0 + 32 <= end; j0 += 32) {
        int sv = g_elist[j0 + lane];
#pragma unroll 8
        for (int k = 0; k < 32; k++) {
            int s = __shfl_sync(~0u, sv, k);
            float t = g_t1[(size_t)(j0 + k) * 4 + myhead];
            ull wd; PACK2(wd, t);
            uint4 v = *(const uint4*)(xh + (size_t)s * 256 + c0);
            FMA2(acc[0], ((ull*)&v)[0], wd);
            FMA2(acc[1], ((ull*)&v)[1], wd);
        }
    }
    if (j0 < end) {
        int sv = (j0 + lane < end) ? g_elist[j0 + lane] : 0;
        int cnt = end - j0;
        for (int k = 0; k < cnt; k++) {
            int s = __shfl_sync(~0u, sv, k);
            float t = g_t1[(size_t)(j0 + k) * 4 + myhead];
            ull wd; PACK2(wd, t);
            uint4 v = *(const uint4*)(xh + (size_t)s * 256 + c0);
            FMA2(acc[0], ((ull*)&v)[0], wd);
            FMA2(acc[1], ((ull*)&v)[1], wd);
        }
    }
    // epilogue: *inv, +bias, ELU, bf16 hi/lo split store (4 cols)
    float o[4];
#pragma unroll
    for (int i = 0; i < 2; i++) {
        unsigned lo_, hi_;
        UNPACK2(lo_, hi_, acc[i]);
        float v0 = __uint_as_float(lo_) * myinv + bias[c0 + 2 * i];
        float v1 = __uint_as_float(hi_) * myinv + bias[c0 + 2 * i + 1];
        o[2 * i] = v0 > 0.f ? v0 : expm1f(v0);
        o[2 * i + 1] = v1 > 0.f ? v1 : expm1f(v1);
    }
    __nv_bfloat16 hb[4], lb[4];
#pragma unroll
    for (int i = 0; i < 4; i++) {
        hb[i] = __float2bfloat16_rn(o[i]);
        lb[i] = __float2bfloat16_rn(o[i] - __bfloat162float(hb[i]));
    }
    *(ull*)&h2b[(size_t)node * 512 + c0] = *(ull*)hb;
    *(ull*)&h2b[(size_t)node * 512 + 256 + c0] = *(ull*)lb;
}

// ---------------- fused softmax+gather layer2 ---------------------------------------
__global__ void gat_agg2(const float* __restrict__ xh, const float* __restrict__ als,
                         const float* __restrict__ ald, const float* __restrict__ bias,
                         float* __restrict__ out) {
    int node = (blockIdx.x * blockDim.x + threadIdx.x) >> 5;
    if (node >= NV) return;
    int lane = threadIdx.x & 31;
    int beg = g_rowptr[node], end = g_rowptr[node + 1];
    float av = ald[node];

    float den = 0.f;
    for (int j = beg + lane; j < end; j += 32) {
        float t = __expf(lrelu(als[g_elist[j]] + av));
        g_t2[j] = t; den += t;
    }
#pragma unroll
    for (int o = 16; o; o >>= 1) den += __shfl_xor_sync(~0u, den, o);
    float inv = 1.f / (den + 1e-16f);
    __syncwarp();

    ull acc = 0;
    int j0 = beg;
    for (; j0 + 32 <= end; j0 += 32) {
        int sv = g_elist[j0 + lane];
        float tv = g_t2[j0 + lane];
#pragma unroll 8
        for (int k = 0; k < 32; k++) {
            int s = __shfl_sync(~0u, sv, k);
            float t = __shfl_sync(~0u, tv, k);
            ull wd; PACK2(wd, t);
            FMA2(acc, *(const ull*)(xh + (size_t)s * 64 + lane * 2), wd);
        }
    }
    if (j0 < end) {
        int sv = (j0 + lane < end) ? g_elist[j0 + lane] : 0;
        float tv = (j0 + lane < end) ? g_t2[j0 + lane] : 0.f;
        int cnt = end - j0;
        for (int k = 0; k < cnt; k++) {
            int s = __shfl_sync(~0u, sv, k);
            float t = __shfl_sync(~0u, tv, k);
            ull wd; PACK2(wd, t);
            FMA2(acc, *(const ull*)(xh + (size_t)s * 64 + lane * 2), wd);
        }
    }
    unsigned lo, hi;
    UNPACK2(lo, hi, acc);
    int c = lane * 2;
    float v0 = __uint_as_float(lo) * inv + bias[c];
    float v1 = __uint_as_float(hi) * inv + bias[c + 1];
    *(float2*)(out + (size_t)node * 64 + c) =
        make_float2(v0 > 0.f ? v0 : expm1f(v0), v1 > 0.f ? v1 : expm1f(v1));
}

// ---------------- launch ---------------------------------------------------------------
extern "C" void kernel_launch(void* const* d_in, const int* in_sizes, int n_in,
                              void* d_out, int out_size) {
    const float* x     = (const float*)d_in[0];
    const int*   ei    = (const int*)d_in[1];
    const float* W1    = (const float*)d_in[2];
    const float* asrc1 = (const float*)d_in[3];
    const float* adst1 = (const float*)d_in[4];
    const float* b1    = (const float*)d_in[5];
    const float* W2    = (const float*)d_in[6];
    const float* asrc2 = (const float*)d_in[7];
    const float* adst2 = (const float*)d_in[8];
    const float* b2    = (const float*)d_in[9];
    float* out = (float*)d_out;

    float *xh1, *xh2, *als1, *ald1, *als2, *ald2;
    __nv_bfloat16 *w1b, *w2b, *xb, *h2b;
    cudaGetSymbolAddress((void**)&xh1, g_xh1);
    cudaGetSymbolAddress((void**)&xh2, g_xh2);
    cudaGetSymbolAddress((void**)&als1, g_als1);
    cudaGetSymbolAddress((void**)&ald1, g_ald1);
    cudaGetSymbolAddress((void**)&als2, g_als2);
    cudaGetSymbolAddress((void**)&ald2, g_ald2);
    cudaGetSymbolAddress((void**)&w1b, g_w1b);
    cudaGetSymbolAddress((void**)&w2b, g_w2b);
    cudaGetSymbolAddress((void**)&xb, g_xb);
    cudaGetSymbolAddress((void**)&h2b, g_h2b);

    static cudaStream_t sCsr = nullptr;
    static cudaEvent_t ev0 = nullptr, ev1 = nullptr;
    if (!sCsr) {
        cudaStreamCreateWithFlags(&sCsr, cudaStreamNonBlocking);
        cudaEventCreateWithFlags(&ev0, cudaEventDisableTiming);
        cudaEventCreateWithFlags(&ev1, cudaEventDisableTiming);
    }

    const int TB = 256;

    // ---- side stream: CSR build + W2 conversion (not needed until after join) ----
    cudaEventRecord(ev0, 0);
    cudaStreamWaitEvent(sCsr, ev0, 0);
    deg_init<<<(NV + TB - 1) / TB, TB, 0, sCsr>>>();
    deg_hist<<<(EE + TB - 1) / TB, TB, 0, sCsr>>>(ei);
    scan_k<<<1, 1024, 0, sCsr>>>();
    scatter_k<<<(ET + TB - 1) / TB, TB, 0, sCsr>>>(ei);
    convW<<<(256 * 64 + TB - 1) / TB, TB, 0, sCsr>>>(W2, w2b, 64);
    cudaEventRecord(ev1, sCsr);

    // ---- main chain ----
    convX<<<(NV * 64 + TB - 1) / TB, TB>>>(x, xb);
    convW<<<(256 * 256 + TB - 1) / TB, TB>>>(W1, w1b, 256);

    gemm_mma<4><<<dim3(4, (NV + 127) / 128), 256>>>(
        xb, w1b, xh1, asrc1, adst1, als1, ald1, NV, 256);

    cudaStreamWaitEvent(0, ev1, 0);
    gat_agg1<<<(NV * 64 + TB - 1) / TB, TB>>>(xh1, als1, ald1, b1, h2b);

    gemm_mma<1><<<dim3(1, (NV + 127) / 128), 256>>>(
        h2b, w2b, xh2, asrc2, adst2, als2, ald2, NV, 64);
    gat_agg2<<<(NV * 32 + TB - 1) / TB, TB>>>(xh2, als2, ald2, b2, out);
}